// round 8
// baseline (speedup 1.0000x reference)
#include <cuda_runtime.h>
#include <cuda_bf16.h>

#define N_ATOMS   5000
#define N_EDGES   200000
#define N_TRIPLES 4000000
#define D_NODE    128
#define D_EDGE    128
#define N_BASIS   9

// Scratch (no allocations allowed)
__device__ float g_atoms[N_ATOMS * N_BASIS];      // sigmoid(node@W_atom+b) [5000 x 9]
__device__ float g_new_bonds[N_EDGES * N_BASIS];  // segment sums           [200000 x 9]
__device__ int   g_seg_start[N_EDGES + 1];        // run boundaries in sorted seg_ids
__device__ int   g_end_atom[N_TRIPLES];           // graph_dst[lg_dst[t]]   (precomputed)

// ---------------------------------------------------------------------------
// Kernel 1: atoms = sigmoid(node_feat @ W_atom + b_atom)   [5000 x 9]
// ---------------------------------------------------------------------------
__global__ void atoms_kernel(const float* __restrict__ node_feat,
                             const float* __restrict__ W_atom,
                             const float* __restrict__ b_atom) {
    int id = blockIdx.x * blockDim.x + threadIdx.x;
    if (id >= N_ATOMS * N_BASIS) return;
    int a = id / N_BASIS;
    int j = id % N_BASIS;
    float acc = b_atom[j];
    const float* nf = node_feat + a * D_NODE;
    #pragma unroll 8
    for (int k = 0; k < D_NODE; k++)
        acc = fmaf(nf[k], W_atom[k * N_BASIS + j], acc);
    g_atoms[id] = 1.0f / (1.0f + __expf(-acc));
}

// ---------------------------------------------------------------------------
// Kernel 1b: seg_start[e] = lower_bound(seg_ids, e)  (seg_ids is sorted)
// ---------------------------------------------------------------------------
__global__ void seg_start_kernel(const int* __restrict__ seg_ids) {
    int e = blockIdx.x * blockDim.x + threadIdx.x;
    if (e > N_EDGES) return;
    if (e == N_EDGES) { g_seg_start[N_EDGES] = N_TRIPLES; return; }
    int lo = 0, hi = N_TRIPLES;
    while (lo < hi) {
        int mid = (lo + hi) >> 1;
        if (__ldg(seg_ids + mid) < e) lo = mid + 1; else hi = mid;
    }
    g_seg_start[e] = lo;
}

// ---------------------------------------------------------------------------
// Kernel 1c: end_atom[t] = graph_dst[lg_dst[t]]
// Streaming two-hop gather with unbounded MLP (one thread per triple).
// Removes the dependent-load chain from the hot triples loop.
// ---------------------------------------------------------------------------
__global__ void gather_kernel(const int* __restrict__ lg_dst,
                              const int* __restrict__ graph_dst) {
    int t = blockIdx.x * blockDim.x + threadIdx.x;
    if (t < N_TRIPLES)
        g_end_atom[t] = __ldg(graph_dst + __ldg(lg_dst + t));
}

// ---------------------------------------------------------------------------
// Kernel 2 (v6, WARP-PER-EDGE, pipelined, no dependent gather):
//
// Warp owns edge e with contiguous triple run [s, s+len). Lanes 0..26:
// group g = lane/9 handles triple s+3k+g, column j = lane%9. Per step the
// warp loads 27 CONSECUTIVE floats of three_basis and a converged contiguous
// int from g_end_atom. Predication-as-select (no branch) + pointer induction
// + unroll 2 -> two steps of independent loads in flight.
// Epilogue: 2 shuffles + one coalesced 9-float plain store. Zero atomics.
//
// smem = fp32 atoms table (180 KB); TPB 1024 -> 32 warps/SM.
// ---------------------------------------------------------------------------
#define TPB_T    1024
#define GRID_T   148
#define NWARPS_T (GRID_T * (TPB_T / 32))      // 4736
#define SMEM_T_BYTES (N_ATOMS * N_BASIS * 4)  // 180000

__global__ __launch_bounds__(TPB_T) void triples_kernel(
    const float* __restrict__ three_basis) {

    extern __shared__ float s_atoms[];   // 45000 floats
    for (int i = threadIdx.x; i < N_ATOMS * N_BASIS; i += TPB_T)
        s_atoms[i] = g_atoms[i];
    __syncthreads();

    const int lane   = threadIdx.x & 31;
    const int group  = lane / 9;               // 0,1,2 (3 for lanes 27..31)
    const int j      = lane - group * 9;       // basis column
    const bool active = (lane < 27);
    const int warp_global = blockIdx.x * (TPB_T / 32) + (threadIdx.x >> 5);

    for (int e = warp_global; e < N_EDGES; e += NWARPS_T) {
        const int s   = g_seg_start[e];
        const int len = g_seg_start[e + 1] - s;

        const float* tbp = three_basis + (size_t)s * 9 + lane;  // +27/step
        const int*   eap = g_end_atom + s + group;              // +3/step

        float acc = 0.f;
        #pragma unroll 2
        for (int k = 0; k < len; k += 3) {
            const bool p = active && (k + group) < len;
            // predicated loads, no branch -> unrollable / pipelineable
            float val = p ? __ldg(tbp + 9 * k) : 0.f;
            int   ei  = p ? __ldg(eap + k)     : 0;
            acc = fmaf(val, s_atoms[ei * N_BASIS + j], acc);
        }

        // reduce 3 groups onto lanes 0..8
        float a1 = __shfl_down_sync(0xFFFFFFFFu, acc, 9);
        float a2 = __shfl_down_sync(0xFFFFFFFFu, acc, 18);
        if (lane < N_BASIS)
            g_new_bonds[(size_t)e * N_BASIS + lane] = acc + a1 + a2;
    }
}

// ---------------------------------------------------------------------------
// Kernel 3: out = edge_feat + silu(g)*sigmoid(s)   (best measured version)
// ---------------------------------------------------------------------------
#define E_TILE   64
#define NB_TILE  (E_TILE * N_BASIS)            // 576 floats
#define N_TILES  (N_EDGES / E_TILE)            // 3125
#define MLP_GRID 1184                          // 8 blocks/SM * 148

__global__ __launch_bounds__(D_EDGE) void mlp_kernel(
    const float* __restrict__ edge_feat,
    const float* __restrict__ W_gate, const float* __restrict__ b_gate,
    const float* __restrict__ W_sig,  const float* __restrict__ b_sig,
    float* __restrict__ out) {

    __shared__ float s_nb[NB_TILE];

    const int j = threadIdx.x;

    float wg[N_BASIS], ws[N_BASIS];
    #pragma unroll
    for (int k = 0; k < N_BASIS; k++) {
        wg[k] = W_gate[k * D_EDGE + j];
        ws[k] = W_sig [k * D_EDGE + j];
    }
    const float bg = b_gate[j];
    const float bs = b_sig[j];

    for (int tile = blockIdx.x; tile < N_TILES; tile += MLP_GRID) {
        const int e0 = tile * E_TILE;

        __syncthreads();
        const float* nb_src = g_new_bonds + (size_t)e0 * N_BASIS;
        #pragma unroll
        for (int i = j; i < NB_TILE; i += D_EDGE)
            s_nb[i] = nb_src[i];
        __syncthreads();

        #pragma unroll 2
        for (int e = 0; e < E_TILE; e += 2) {
            const float* nb0 = s_nb + e * N_BASIS;
            const float* nb1 = nb0 + N_BASIS;

            size_t idx0 = (size_t)(e0 + e) * D_EDGE + j;
            size_t idx1 = idx0 + D_EDGE;
            float ef0 = edge_feat[idx0];
            float ef1 = edge_feat[idx1];

            float g0 = bg, s0 = bs, g1 = bg, s1 = bs;
            #pragma unroll
            for (int k = 0; k < N_BASIS; k++) {
                float n0 = nb0[k], n1 = nb1[k];
                g0 = fmaf(n0, wg[k], g0);
                s0 = fmaf(n0, ws[k], s0);
                g1 = fmaf(n1, wg[k], g1);
                s1 = fmaf(n1, ws[k], s1);
            }
            // up = g / ((1+e^-g)(1+e^-s)) == silu(g)*sigmoid(s)
            float d0 = (1.f + __expf(-g0)) * (1.f + __expf(-s0));
            float d1 = (1.f + __expf(-g1)) * (1.f + __expf(-s1));
            out[idx0] = ef0 + __fdividef(g0, d0);
            out[idx1] = ef1 + __fdividef(g1, d1);
        }
    }
}

// ---------------------------------------------------------------------------
// Launch
// ---------------------------------------------------------------------------
extern "C" void kernel_launch(void* const* d_in, const int* in_sizes, int n_in,
                              void* d_out, int out_size) {
    const float* node_feat   = (const float*)d_in[0];
    const float* edge_feat   = (const float*)d_in[1];
    const float* three_basis = (const float*)d_in[2];
    const float* W_atom      = (const float*)d_in[4];
    const float* b_atom      = (const float*)d_in[5];
    const float* W_gate      = (const float*)d_in[6];
    const float* b_gate      = (const float*)d_in[7];
    const float* W_sig       = (const float*)d_in[8];
    const float* b_sig       = (const float*)d_in[9];
    const int*   graph_dst   = (const int*)d_in[10];
    const int*   lg_dst      = (const int*)d_in[12];
    const int*   seg_ids     = (const int*)d_in[13];
    float*       out         = (float*)d_out;

    cudaFuncSetAttribute(triples_kernel,
                         cudaFuncAttributeMaxDynamicSharedMemorySize, SMEM_T_BYTES);

    atoms_kernel<<<(N_ATOMS * N_BASIS + 255) / 256, 256>>>(node_feat, W_atom, b_atom);
    seg_start_kernel<<<(N_EDGES + 1 + 255) / 256, 256>>>(seg_ids);
    gather_kernel<<<(N_TRIPLES + 511) / 512, 512>>>(lg_dst, graph_dst);
    triples_kernel<<<GRID_T, TPB_T, SMEM_T_BYTES>>>(three_basis);
    mlp_kernel<<<MLP_GRID, D_EDGE>>>(edge_feat, W_gate, b_gate, W_sig, b_sig, out);
}

// round 9
// speedup vs baseline: 1.2328x; 1.2328x over previous
#include <cuda_runtime.h>
#include <cuda_bf16.h>

#define N_ATOMS   5000
#define N_EDGES   200000
#define N_TRIPLES 4000000
#define D_NODE    128
#define D_EDGE    128
#define N_BASIS   9

// Scratch (no allocations allowed)
__device__ float g_atoms[N_ATOMS * N_BASIS];      // sigmoid(node@W_atom+b) [5000 x 9]
__device__ float g_new_bonds[N_EDGES * N_BASIS];  // segment sums           [200000 x 9]
__device__ int   g_seg_start[N_EDGES + 1];        // run boundaries in sorted seg_ids

// ---------------------------------------------------------------------------
// Kernel 1: atoms = sigmoid(node_feat @ W_atom + b_atom)   [5000 x 9]
// ---------------------------------------------------------------------------
__global__ void atoms_kernel(const float* __restrict__ node_feat,
                             const float* __restrict__ W_atom,
                             const float* __restrict__ b_atom) {
    int id = blockIdx.x * blockDim.x + threadIdx.x;
    if (id >= N_ATOMS * N_BASIS) return;
    int a = id / N_BASIS;
    int j = id % N_BASIS;
    float acc = b_atom[j];
    const float* nf = node_feat + a * D_NODE;
    #pragma unroll 8
    for (int k = 0; k < D_NODE; k++)
        acc = fmaf(nf[k], W_atom[k * N_BASIS + j], acc);
    g_atoms[id] = 1.0f / (1.0f + __expf(-acc));
}

// ---------------------------------------------------------------------------
// Kernel 1b: seg_start[e] = lower_bound(seg_ids, e)  (seg_ids is sorted)
// ---------------------------------------------------------------------------
__global__ void seg_start_kernel(const int* __restrict__ seg_ids) {
    int e = blockIdx.x * blockDim.x + threadIdx.x;
    if (e > N_EDGES) return;
    if (e == N_EDGES) { g_seg_start[N_EDGES] = N_TRIPLES; return; }
    int lo = 0, hi = N_TRIPLES;
    while (lo < hi) {
        int mid = (lo + hi) >> 1;
        if (__ldg(seg_ids + mid) < e) lo = mid + 1; else hi = mid;
    }
    g_seg_start[e] = lo;
}

// ---------------------------------------------------------------------------
// Kernel 2 (v7, WARP-PER-EDGE with DEEP BATCHED PREFETCH):
//
// Warp owns edge e with contiguous triple run [s, s+len). 27 active lanes:
// group g = lane/9 -> triple s+3k+g, column j = lane%9.
//
// The inner loop is a BATCH of 8 steps (24 triples): all 8 three_basis LDGs
// and all 8 lg_dst LDGs are issued back-to-back (independent, predicated
// selects -> no branches), then 8 graph_dst LDGs, then 8 LDS+FMA. This
// raises per-warp outstanding loads from ~2 to ~16, cutting the effective
// DRAM stream latency (577/MLP) ~8x. Most edges (len~Poisson(20)) finish in
// 1-2 batches. Epilogue: 2 shuffles + coalesced 9-float plain store.
// Zero atomics, warp-uniform loop bounds.
//
// smem = fp32 atoms table (180 KB); TPB 1024 -> 32 warps/SM.
// ---------------------------------------------------------------------------
#define TPB_T    1024
#define GRID_T   148
#define NWARPS_T (GRID_T * (TPB_T / 32))      // 4736
#define SMEM_T_BYTES (N_ATOMS * N_BASIS * 4)  // 180000
#define UB 8                                  // batch steps (24 triples)

__global__ __launch_bounds__(TPB_T) void triples_kernel(
    const float* __restrict__ three_basis,
    const int*   __restrict__ graph_dst,
    const int*   __restrict__ lg_dst) {

    extern __shared__ float s_atoms[];   // 45000 floats
    for (int i = threadIdx.x; i < N_ATOMS * N_BASIS; i += TPB_T)
        s_atoms[i] = g_atoms[i];
    __syncthreads();

    const int lane   = threadIdx.x & 31;
    const int group  = lane / 9;               // 0,1,2 (3 for lanes 27..31)
    const int j      = lane - group * 9;       // basis column
    const bool active = (lane < 27);
    const int warp_global = blockIdx.x * (TPB_T / 32) + (threadIdx.x >> 5);

    for (int e = warp_global; e < N_EDGES; e += NWARPS_T) {
        const int s   = __ldg(g_seg_start + e);
        const int len = __ldg(g_seg_start + e + 1) - s;

        const float* tbp = three_basis + (size_t)s * 9 + lane;  // +27/step
        const int*   lgp = lg_dst + s + group;                  // +3/step

        float acc = 0.f;
        for (int k0 = 0; k0 < len; k0 += 3 * UB) {
            float v[UB];
            int   lgv[UB];
            bool  p[UB];

            // phase 1: issue all independent streaming loads (MLP ~16)
            #pragma unroll
            for (int u = 0; u < UB; u++) {
                const int k = k0 + 3 * u;
                p[u]   = active && (k + group) < len;
                v[u]   = p[u] ? __ldg(tbp + 9 * k) : 0.f;
                lgv[u] = p[u] ? __ldg(lgp + k)     : 0;
            }
            // phase 2: second-hop gathers (independent, L2-resident)
            int ei[UB];
            #pragma unroll
            for (int u = 0; u < UB; u++)
                ei[u] = p[u] ? __ldg(graph_dst + lgv[u]) : 0;
            // phase 3: smem atom rows + FMA
            #pragma unroll
            for (int u = 0; u < UB; u++)
                acc = fmaf(v[u], s_atoms[ei[u] * N_BASIS + j], acc);
        }

        // reduce 3 groups onto lanes 0..8
        float a1 = __shfl_down_sync(0xFFFFFFFFu, acc, 9);
        float a2 = __shfl_down_sync(0xFFFFFFFFu, acc, 18);
        if (lane < N_BASIS)
            g_new_bonds[(size_t)e * N_BASIS + lane] = acc + a1 + a2;
    }
}

// ---------------------------------------------------------------------------
// Kernel 3: out = edge_feat + silu(g)*sigmoid(s)   (best measured version)
// ---------------------------------------------------------------------------
#define E_TILE   64
#define NB_TILE  (E_TILE * N_BASIS)            // 576 floats
#define N_TILES  (N_EDGES / E_TILE)            // 3125
#define MLP_GRID 1184                          // 8 blocks/SM * 148

__global__ __launch_bounds__(D_EDGE) void mlp_kernel(
    const float* __restrict__ edge_feat,
    const float* __restrict__ W_gate, const float* __restrict__ b_gate,
    const float* __restrict__ W_sig,  const float* __restrict__ b_sig,
    float* __restrict__ out) {

    __shared__ float s_nb[NB_TILE];

    const int j = threadIdx.x;

    float wg[N_BASIS], ws[N_BASIS];
    #pragma unroll
    for (int k = 0; k < N_BASIS; k++) {
        wg[k] = W_gate[k * D_EDGE + j];
        ws[k] = W_sig [k * D_EDGE + j];
    }
    const float bg = b_gate[j];
    const float bs = b_sig[j];

    for (int tile = blockIdx.x; tile < N_TILES; tile += MLP_GRID) {
        const int e0 = tile * E_TILE;

        __syncthreads();
        const float* nb_src = g_new_bonds + (size_t)e0 * N_BASIS;
        #pragma unroll
        for (int i = j; i < NB_TILE; i += D_EDGE)
            s_nb[i] = nb_src[i];
        __syncthreads();

        #pragma unroll 2
        for (int e = 0; e < E_TILE; e += 2) {
            const float* nb0 = s_nb + e * N_BASIS;
            const float* nb1 = nb0 + N_BASIS;

            size_t idx0 = (size_t)(e0 + e) * D_EDGE + j;
            size_t idx1 = idx0 + D_EDGE;
            float ef0 = edge_feat[idx0];
            float ef1 = edge_feat[idx1];

            float g0 = bg, s0 = bs, g1 = bg, s1 = bs;
            #pragma unroll
            for (int k = 0; k < N_BASIS; k++) {
                float n0 = nb0[k], n1 = nb1[k];
                g0 = fmaf(n0, wg[k], g0);
                s0 = fmaf(n0, ws[k], s0);
                g1 = fmaf(n1, wg[k], g1);
                s1 = fmaf(n1, ws[k], s1);
            }
            // up = g / ((1+e^-g)(1+e^-s)) == silu(g)*sigmoid(s)
            float d0 = (1.f + __expf(-g0)) * (1.f + __expf(-s0));
            float d1 = (1.f + __expf(-g1)) * (1.f + __expf(-s1));
            out[idx0] = ef0 + __fdividef(g0, d0);
            out[idx1] = ef1 + __fdividef(g1, d1);
        }
    }
}

// ---------------------------------------------------------------------------
// Launch
// ---------------------------------------------------------------------------
extern "C" void kernel_launch(void* const* d_in, const int* in_sizes, int n_in,
                              void* d_out, int out_size) {
    const float* node_feat   = (const float*)d_in[0];
    const float* edge_feat   = (const float*)d_in[1];
    const float* three_basis = (const float*)d_in[2];
    const float* W_atom      = (const float*)d_in[4];
    const float* b_atom      = (const float*)d_in[5];
    const float* W_gate      = (const float*)d_in[6];
    const float* b_gate      = (const float*)d_in[7];
    const float* W_sig       = (const float*)d_in[8];
    const float* b_sig       = (const float*)d_in[9];
    const int*   graph_dst   = (const int*)d_in[10];
    const int*   lg_dst      = (const int*)d_in[12];
    const int*   seg_ids     = (const int*)d_in[13];
    float*       out         = (float*)d_out;

    cudaFuncSetAttribute(triples_kernel,
                         cudaFuncAttributeMaxDynamicSharedMemorySize, SMEM_T_BYTES);

    atoms_kernel<<<(N_ATOMS * N_BASIS + 255) / 256, 256>>>(node_feat, W_atom, b_atom);
    seg_start_kernel<<<(N_EDGES + 1 + 255) / 256, 256>>>(seg_ids);
    triples_kernel<<<GRID_T, TPB_T, SMEM_T_BYTES>>>(three_basis, graph_dst, lg_dst);
    mlp_kernel<<<MLP_GRID, D_EDGE>>>(edge_feat, W_gate, b_gate, W_sig, b_sig, out);
}

// round 10
// speedup vs baseline: 1.4032x; 1.1382x over previous
#include <cuda_runtime.h>
#include <cuda_fp16.h>
#include <cuda_bf16.h>

#define N_ATOMS   5000
#define N_EDGES   200000
#define N_TRIPLES 4000000
#define D_NODE    128
#define D_EDGE    128
#define N_BASIS   9

// Scratch (no allocations allowed)
__device__ __half g_atoms_h[N_ATOMS * N_BASIS];   // fp16 atoms table [5000 x 9]
__device__ float  g_new_bonds[N_EDGES * N_BASIS]; // segment sums     [200000 x 9]
__device__ int    g_seg_start[N_EDGES + 1];       // run boundaries in sorted seg_ids

// ---------------------------------------------------------------------------
// Kernel 1: atoms = sigmoid(node_feat @ W_atom + b_atom), stored fp16
// ---------------------------------------------------------------------------
__global__ void atoms_kernel(const float* __restrict__ node_feat,
                             const float* __restrict__ W_atom,
                             const float* __restrict__ b_atom) {
    int id = blockIdx.x * blockDim.x + threadIdx.x;
    if (id >= N_ATOMS * N_BASIS) return;
    int a = id / N_BASIS;
    int j = id % N_BASIS;
    float acc = b_atom[j];
    const float* nf = node_feat + a * D_NODE;
    #pragma unroll 8
    for (int k = 0; k < D_NODE; k++)
        acc = fmaf(nf[k], W_atom[k * N_BASIS + j], acc);
    g_atoms_h[id] = __float2half_rn(1.0f / (1.0f + __expf(-acc)));
}

// ---------------------------------------------------------------------------
// Kernel 1b: seg_start[e] = lower_bound(seg_ids, e)  (seg_ids is sorted)
// ---------------------------------------------------------------------------
__global__ void seg_start_kernel(const int* __restrict__ seg_ids) {
    int e = blockIdx.x * blockDim.x + threadIdx.x;
    if (e > N_EDGES) return;
    if (e == N_EDGES) { g_seg_start[N_EDGES] = N_TRIPLES; return; }
    int lo = 0, hi = N_TRIPLES;
    while (lo < hi) {
        int mid = (lo + hi) >> 1;
        if (__ldg(seg_ids + mid) < e) lo = mid + 1; else hi = mid;
    }
    g_seg_start[e] = lo;
}

// ---------------------------------------------------------------------------
// Kernel 2 (v8): warp-per-edge, batched prefetch, FP16 atoms table.
//
// fp16 table = 90 KB/block -> 2 blocks x 1024 threads per SM = 64 warps
// (100% occupancy; was capped at 50% by the 180 KB fp32 table).
// __launch_bounds__(1024, 2) pins regs <= 32 so both blocks fit.
//
// 27 active lanes: group g = lane/9 -> triple s+3k+g, column j = lane%9.
// Batch of 8 steps: 8 independent tb LDGs + 8 independent lg->graph 2-hop
// chains in flight, then 8 LDS(fp16)->cvt->FMA. Epilogue: 2 shuffles + one
// coalesced 9-float plain store. Zero atomics, warp-uniform loop bounds.
// ---------------------------------------------------------------------------
#define TPB_T    1024
#define GRID_T   296                           // 2 blocks/SM x 148
#define NWARPS_T (GRID_T * (TPB_T / 32))       // 9472
#define SMEM_T_BYTES (N_ATOMS * N_BASIS * 2)   // 90000
#define UB 8

__global__ __launch_bounds__(TPB_T, 2) void triples_kernel(
    const float* __restrict__ three_basis,
    const int*   __restrict__ graph_dst,
    const int*   __restrict__ lg_dst) {

    extern __shared__ __half s_atoms[];   // 45000 halfs
    for (int i = threadIdx.x; i < N_ATOMS * N_BASIS; i += TPB_T)
        s_atoms[i] = g_atoms_h[i];
    __syncthreads();

    const int lane   = threadIdx.x & 31;
    const int group  = lane / 9;               // 0,1,2 (3 for lanes 27..31)
    const int j      = lane - group * 9;       // basis column
    const bool active = (lane < 27);
    const int warp_global = blockIdx.x * (TPB_T / 32) + (threadIdx.x >> 5);

    for (int e = warp_global; e < N_EDGES; e += NWARPS_T) {
        const int s   = __ldg(g_seg_start + e);
        const int len = __ldg(g_seg_start + e + 1) - s;

        const float* tbp = three_basis + (size_t)s * 9 + lane;  // +27/step
        const int*   lgp = lg_dst + s + group;                  // +3/step

        float acc = 0.f;
        for (int k0 = 0; k0 < len; k0 += 3 * UB) {
            float v[UB];
            int   ei[UB];

            // 8 independent streaming loads + 8 independent 2-hop chains
            #pragma unroll
            for (int u = 0; u < UB; u++) {
                const int k = k0 + 3 * u;
                const bool p = active && (k + group) < len;
                v[u]  = p ? __ldg(tbp + 9 * k) : 0.f;
                ei[u] = p ? __ldg(graph_dst + __ldg(lgp + k)) : 0;
            }
            #pragma unroll
            for (int u = 0; u < UB; u++)
                acc = fmaf(v[u], __half2float(s_atoms[ei[u] * N_BASIS + j]), acc);
        }

        // reduce 3 groups onto lanes 0..8
        float a1 = __shfl_down_sync(0xFFFFFFFFu, acc, 9);
        float a2 = __shfl_down_sync(0xFFFFFFFFu, acc, 18);
        if (lane < N_BASIS)
            g_new_bonds[(size_t)e * N_BASIS + lane] = acc + a1 + a2;
    }
}

// ---------------------------------------------------------------------------
// Kernel 3: out = edge_feat + silu(g)*sigmoid(s)
// Grid doubled to 2368 (16 blocks/SM = 2048 threads) to lift the 50% occ cap.
// ---------------------------------------------------------------------------
#define E_TILE   64
#define NB_TILE  (E_TILE * N_BASIS)            // 576 floats
#define N_TILES  (N_EDGES / E_TILE)            // 3125
#define MLP_GRID 2368                          // 16 blocks/SM * 148

__global__ __launch_bounds__(D_EDGE) void mlp_kernel(
    const float* __restrict__ edge_feat,
    const float* __restrict__ W_gate, const float* __restrict__ b_gate,
    const float* __restrict__ W_sig,  const float* __restrict__ b_sig,
    float* __restrict__ out) {

    __shared__ float s_nb[NB_TILE];

    const int j = threadIdx.x;

    float wg[N_BASIS], ws[N_BASIS];
    #pragma unroll
    for (int k = 0; k < N_BASIS; k++) {
        wg[k] = W_gate[k * D_EDGE + j];
        ws[k] = W_sig [k * D_EDGE + j];
    }
    const float bg = b_gate[j];
    const float bs = b_sig[j];

    for (int tile = blockIdx.x; tile < N_TILES; tile += MLP_GRID) {
        const int e0 = tile * E_TILE;

        __syncthreads();
        const float* nb_src = g_new_bonds + (size_t)e0 * N_BASIS;
        #pragma unroll
        for (int i = j; i < NB_TILE; i += D_EDGE)
            s_nb[i] = nb_src[i];
        __syncthreads();

        #pragma unroll 2
        for (int e = 0; e < E_TILE; e += 2) {
            const float* nb0 = s_nb + e * N_BASIS;
            const float* nb1 = nb0 + N_BASIS;

            size_t idx0 = (size_t)(e0 + e) * D_EDGE + j;
            size_t idx1 = idx0 + D_EDGE;
            float ef0 = edge_feat[idx0];
            float ef1 = edge_feat[idx1];

            float g0 = bg, s0 = bs, g1 = bg, s1 = bs;
            #pragma unroll
            for (int k = 0; k < N_BASIS; k++) {
                float n0 = nb0[k], n1 = nb1[k];
                g0 = fmaf(n0, wg[k], g0);
                s0 = fmaf(n0, ws[k], s0);
                g1 = fmaf(n1, wg[k], g1);
                s1 = fmaf(n1, ws[k], s1);
            }
            // up = g / ((1+e^-g)(1+e^-s)) == silu(g)*sigmoid(s)
            float d0 = (1.f + __expf(-g0)) * (1.f + __expf(-s0));
            float d1 = (1.f + __expf(-g1)) * (1.f + __expf(-s1));
            out[idx0] = ef0 + __fdividef(g0, d0);
            out[idx1] = ef1 + __fdividef(g1, d1);
        }
    }
}

// ---------------------------------------------------------------------------
// Launch
// ---------------------------------------------------------------------------
extern "C" void kernel_launch(void* const* d_in, const int* in_sizes, int n_in,
                              void* d_out, int out_size) {
    const float* node_feat   = (const float*)d_in[0];
    const float* edge_feat   = (const float*)d_in[1];
    const float* three_basis = (const float*)d_in[2];
    const float* W_atom      = (const float*)d_in[4];
    const float* b_atom      = (const float*)d_in[5];
    const float* W_gate      = (const float*)d_in[6];
    const float* b_gate      = (const float*)d_in[7];
    const float* W_sig       = (const float*)d_in[8];
    const float* b_sig       = (const float*)d_in[9];
    const int*   graph_dst   = (const int*)d_in[10];
    const int*   lg_dst      = (const int*)d_in[12];
    const int*   seg_ids     = (const int*)d_in[13];
    float*       out         = (float*)d_out;

    cudaFuncSetAttribute(triples_kernel,
                         cudaFuncAttributeMaxDynamicSharedMemorySize, SMEM_T_BYTES);

    atoms_kernel<<<(N_ATOMS * N_BASIS + 255) / 256, 256>>>(node_feat, W_atom, b_atom);
    seg_start_kernel<<<(N_EDGES + 1 + 255) / 256, 256>>>(seg_ids);
    triples_kernel<<<GRID_T, TPB_T, SMEM_T_BYTES>>>(three_basis, graph_dst, lg_dst);
    mlp_kernel<<<MLP_GRID, D_EDGE>>>(edge_feat, W_gate, b_gate, W_sig, b_sig, out);
}